// round 11
// baseline (speedup 1.0000x reference)
#include <cuda_runtime.h>
#include <cstdint>

#define L       8192
#define CHN     16
#define BATCH   32
#define NSTEPS  100
#define HSTEP   0.01f
#define TILEX   256
#define NTHR    128

typedef unsigned long long ull;

__device__ float g_z [(size_t)BATCH * CHN * L];
__device__ float g_k1[(size_t)BATCH * CHN * L];
__device__ float g_k2[(size_t)BATCH * CHN * L];

__device__ __forceinline__ ull pk2(float lo, float hi) {
    ull r; asm("mov.b64 %0, {%1,%2};" : "=l"(r) : "f"(lo), "f"(hi)); return r;
}
__device__ __forceinline__ void upk2(ull a, float& lo, float& hi) {
    asm("mov.b64 {%0,%1}, %2;" : "=f"(lo), "=f"(hi) : "l"(a));
}
__device__ __forceinline__ void fma2(ull &acc, ull a, ull b) {
    asm("fma.rn.f32x2 %0, %1, %2, %0;" : "+l"(acc) : "l"(a), "l"(b));
}

// Store one 4-wide output chunk with ghost-cell handling.
// Interior formula valid for x in [10, 8181]; ghosts replicate those edges.
__device__ __forceinline__ void store_chunk(float* __restrict__ orow, int x,
                                            float f0, float f1, float f2, float f3) {
    if (x >= 12 && x <= 8176) {
        *(float4*)(orow + x) = make_float4(f0, f1, f2, f3);
    } else if (x == 8) {
        #pragma unroll
        for (int i = 0; i < 10; ++i) orow[i] = f2;
        orow[10] = f2; orow[11] = f3;
    } else if (x == 8180) {
        orow[8180] = f0; orow[8181] = f1;
        #pragma unroll
        for (int i = 0; i < 10; ++i) orow[8182 + i] = f1;
    }
}

// STAGE 1: out = B(z + h conv(z))
// STAGE 2: out = B(0.75 z + 0.25 k + 0.25 h conv(k))
// STAGE 3: out = B(z/3 + 2k/3 + (2h/3) conv(k))
template<int STAGE>
__global__ void __launch_bounds__(NTHR, 6)
stage_k(const float* __restrict__ zin, const float* __restrict__ kin,
        float* __restrict__ out, const float* __restrict__ Wg)
{
    // wd[ci][co][12] : [w0,w0,w1,w1][w2,w2,w3,w3][w4,w4,-,-]
    __shared__ float wd[CHN * CHN * 12];
    const int tid = threadIdx.x;
    for (int i = tid; i < CHN * CHN * 5; i += NTHR) {
        int co = i / 80, r = i % 80, ci = r / 5, t = r % 5;
        float w = Wg[i];
        int base = (ci * 16 + co) * 12;
        wd[base + 2 * t]     = w;
        wd[base + 2 * t + 1] = w;
    }
    __syncthreads();

    const int lane = tid & 31;
    const int w    = tid >> 5;             // 4 warps = 4 cout groups
    const int coo  = w * 4;                // couts coo..coo+3
    const int b    = blockIdx.y;
    const int X0   = blockIdx.x * TILEX;

    const int xA = X0 + 4 * lane;          // segment A chunk
    const int xB = xA + 128;               // segment B chunk

    const int aA0 = (xA - 2 < 0) ? 0 : xA - 2;
    const int aB2 = (xB + 4 > L - 2) ? L - 2 : xB + 4;

    const float* csrc = (STAGE == 1 ? zin : kin) + (size_t)b * CHN * L;

    ull acc[4][4];   // acc[q][p]: lo = out[coo+q][xA+p], hi = out[coo+q][xB+p]
    #pragma unroll
    for (int q = 0; q < 4; ++q)
        #pragma unroll
        for (int j = 0; j < 4; ++j) acc[q][j] = 0ull;

    const float* rowp = csrc;
    #pragma unroll 1
    for (int ci = 0; ci < CHN; ++ci, rowp += L) {
        float2 cA0 = *(const float2*)(rowp + aA0);
        float4 cA1 = *(const float4*)(rowp + xA);
        float2 cA2 = *(const float2*)(rowp + xA + 4);
        float2 cB0 = *(const float2*)(rowp + xB - 2);
        float4 cB1 = *(const float4*)(rowp + xB);
        float2 cB2 = *(const float2*)(rowp + aB2);

        // strided pairs: P[j] = (vA[xA-2+j], vB[xB-2+j]); each value used once
        ull P0 = pk2(cA0.x, cB0.x), P1 = pk2(cA0.y, cB0.y);
        ull P2 = pk2(cA1.x, cB1.x), P3 = pk2(cA1.y, cB1.y);
        ull P4 = pk2(cA1.z, cB1.z), P5 = pk2(cA1.w, cB1.w);
        ull P6 = pk2(cA2.x, cB2.x), P7 = pk2(cA2.y, cB2.y);

        const float* wrow = &wd[(ci * 16 + coo) * 12];
        #pragma unroll
        for (int q = 0; q < 4; ++q) {
            ulonglong2 u01 = *(const ulonglong2*)(wrow + q * 12);
            ulonglong2 u23 = *(const ulonglong2*)(wrow + q * 12 + 4);
            ull W4 = *(const ull*)(wrow + q * 12 + 8);
            ull W0 = u01.x, W1 = u01.y, W2 = u23.x, W3 = u23.y;

            fma2(acc[q][0], P0, W0); fma2(acc[q][0], P1, W1);
            fma2(acc[q][0], P2, W2); fma2(acc[q][0], P3, W3);
            fma2(acc[q][0], P4, W4);
            fma2(acc[q][1], P1, W0); fma2(acc[q][1], P2, W1);
            fma2(acc[q][1], P3, W2); fma2(acc[q][1], P4, W3);
            fma2(acc[q][1], P5, W4);
            fma2(acc[q][2], P2, W0); fma2(acc[q][2], P3, W1);
            fma2(acc[q][2], P4, W2); fma2(acc[q][2], P5, W3);
            fma2(acc[q][2], P6, W4);
            fma2(acc[q][3], P3, W0); fma2(acc[q][3], P4, W1);
            fma2(acc[q][3], P5, W2); fma2(acc[q][3], P6, W3);
            fma2(acc[q][3], P7, W4);
        }
    }

    // ---- epilogue ----
    const float ca = (STAGE == 1) ? 1.0f  : (STAGE == 2) ? 0.75f         : (1.0f / 3.0f);
    const float cb = (STAGE == 1) ? 0.0f  : (STAGE == 2) ? 0.25f         : (2.0f / 3.0f);
    const float cc = (STAGE == 1) ? HSTEP : (STAGE == 2) ? 0.25f * HSTEP : (2.0f * HSTEP / 3.0f);

    const float* zb = zin + (size_t)b * CHN * L;
    const float* kb = (STAGE == 1) ? nullptr : kin + (size_t)b * CHN * L;
    float*       ob = out + (size_t)b * CHN * L;

    #pragma unroll
    for (int q = 0; q < 4; ++q) {
        const int co = coo + q;
        const float* zrow = zb + (size_t)co * L;
        float*       orow = ob + (size_t)co * L;

        float cvA[4], cvB[4];
        #pragma unroll
        for (int p = 0; p < 4; ++p) upk2(acc[q][p], cvA[p], cvB[p]);

        #pragma unroll
        for (int s = 0; s < 2; ++s) {
            const int x = (s == 0) ? xA : xB;
            const float* cv = (s == 0) ? cvA : cvB;

            float4 zv = *(const float4*)(zrow + x);
            float r0, r1, r2, r3;
            if (STAGE == 1) {
                r0 = fmaf(cc, cv[0], zv.x); r1 = fmaf(cc, cv[1], zv.y);
                r2 = fmaf(cc, cv[2], zv.z); r3 = fmaf(cc, cv[3], zv.w);
            } else {
                float4 kv = *(const float4*)(kb + (size_t)co * L + x);
                r0 = fmaf(ca, zv.x, fmaf(cb, kv.x, cc * cv[0]));
                r1 = fmaf(ca, zv.y, fmaf(cb, kv.y, cc * cv[1]));
                r2 = fmaf(ca, zv.z, fmaf(cb, kv.z, cc * cv[2]));
                r3 = fmaf(ca, zv.w, fmaf(cb, kv.w, cc * cv[3]));
            }
            store_chunk(orow, x, r0, r1, r2, r3);
        }
    }
}

extern "C" void kernel_launch(void* const* d_in, const int* in_sizes, int n_in,
                              void* d_out, int out_size) {
    const float* z0 = (const float*)d_in[0];
    const float* W  = (const float*)d_in[1];
    float* out = (float*)d_out;

    float *zscr, *k1, *k2;
    cudaGetSymbolAddress((void**)&zscr, g_z);
    cudaGetSymbolAddress((void**)&k1,   g_k1);
    cudaGetSymbolAddress((void**)&k2,   g_k2);

    dim3 grid(L / TILEX, BATCH);   // (32, 32) = 1024 CTAs of 128 threads
    for (int s = 0; s < NSTEPS; ++s) {
        const float* src;
        float* dst;
        if (s == 0)      { src = z0;   dst = zscr; }
        else if (s & 1)  { src = zscr; dst = out;  }
        else             { src = out;  dst = zscr; }

        stage_k<1><<<grid, NTHR>>>(src, src, k1, W);
        stage_k<2><<<grid, NTHR>>>(src, k1,  k2, W);
        stage_k<3><<<grid, NTHR>>>(src, k2,  dst, W);
    }
}

// round 12
// speedup vs baseline: 1.5566x; 1.5566x over previous
#include <cuda_runtime.h>
#include <cstdint>

#define L       8192
#define CHN     16
#define BATCH   32
#define NSTEPS  100
#define HSTEP   0.01f
#define TILEX   512
#define NTHR    128

typedef unsigned long long ull;

__device__ float g_z [(size_t)BATCH * CHN * L];
__device__ float g_k1[(size_t)BATCH * CHN * L];
__device__ float g_k2[(size_t)BATCH * CHN * L];

__device__ __forceinline__ ull pk2(float lo, float hi) {
    ull r; asm("mov.b64 %0, {%1,%2};" : "=l"(r) : "f"(lo), "f"(hi)); return r;
}
__device__ __forceinline__ void upk2(ull a, float& lo, float& hi) {
    asm("mov.b64 {%0,%1}, %2;" : "=f"(lo), "=f"(hi) : "l"(a));
}
__device__ __forceinline__ void fma2(ull &acc, ull a, ull b) {
    asm("fma.rn.f32x2 %0, %1, %2, %0;" : "+l"(acc) : "l"(a), "l"(b));
}

// Store one 4-wide output chunk with ghost-cell handling.
// Interior formula valid for x in [10, 8181]; ghosts replicate those edges.
__device__ __forceinline__ void store_chunk(float* __restrict__ orow, int x,
                                            float f0, float f1, float f2, float f3) {
    if (x >= 12 && x <= 8176) {
        *(float4*)(orow + x) = make_float4(f0, f1, f2, f3);
    } else if (x == 8) {
        #pragma unroll
        for (int i = 0; i < 10; ++i) orow[i] = f2;
        orow[10] = f2; orow[11] = f3;
    } else if (x == 8180) {
        orow[8180] = f0; orow[8181] = f1;
        #pragma unroll
        for (int i = 0; i < 10; ++i) orow[8182 + i] = f1;
    }
}

// STAGE 1: out = B(z + h conv(z))
// STAGE 2: out = B(0.75 z + 0.25 k + 0.25 h conv(k))
// STAGE 3: out = B(z/3 + 2k/3 + (2h/3) conv(k))
template<int STAGE>
__global__ void __launch_bounds__(NTHR, 4)
stage_k(const float* __restrict__ zin, const float* __restrict__ kin,
        float* __restrict__ out, const float* __restrict__ Wg)
{
    // wd[ci][co][12] : [w0,w0,w1,w1][w2,w2,w3,w3][w4,w4,-,-]
    __shared__ float wd[CHN * CHN * 12];
    const int tid = threadIdx.x;
    for (int i = tid; i < CHN * CHN * 5; i += NTHR) {
        int co = i / 80, r = i % 80, ci = r / 5, t = r % 5;
        float w = Wg[i];
        int base = (ci * 16 + co) * 12;
        wd[base + 2 * t]     = w;
        wd[base + 2 * t + 1] = w;
    }
    __syncthreads();

    const int lane = tid & 31;
    const int w    = tid >> 5;             // 4 warps
    const int coo  = (w & 1) * 8;          // cout base (0 or 8)
    const int sp   = w >> 1;               // segment pair 0/1
    const int b    = blockIdx.y;
    const int X0   = blockIdx.x * TILEX;

    const int xA = X0 + sp * 128 + 4 * lane;   // segment A chunk
    const int xB = xA + 256;                   // segment B chunk

    const int aA0 = (xA - 4 < 0) ? 0 : xA - 4;
    const int aB2 = (xB + 4 > L - 4) ? L - 4 : xB + 4;

    const float* csrc = (STAGE == 1 ? zin : kin) + (size_t)b * CHN * L;

    ull acc[8][4];   // acc[q][p]: lo = out[coo+q][xA+p], hi = out[coo+q][xB+p]
    #pragma unroll
    for (int q = 0; q < 8; ++q)
        #pragma unroll
        for (int j = 0; j < 4; ++j) acc[q][j] = 0ull;

    const float* rowp = csrc;
    float4 cA0 = *(const float4*)(rowp + aA0);
    float4 cA1 = *(const float4*)(rowp + xA);
    float4 cA2 = *(const float4*)(rowp + xA + 4);
    float4 cB0 = *(const float4*)(rowp + xB - 4);
    float4 cB1 = *(const float4*)(rowp + xB);
    float4 cB2 = *(const float4*)(rowp + aB2);

    #pragma unroll 1
    for (int ci = 0; ci < CHN; ++ci) {
        const float* nrow = rowp + L;
        float4 nA0, nA1, nA2, nB0, nB1, nB2;
        if (ci < CHN - 1) {                       // predicated prefetch
            nA0 = *(const float4*)(nrow + aA0);
            nA1 = *(const float4*)(nrow + xA);
            nA2 = *(const float4*)(nrow + xA + 4);
            nB0 = *(const float4*)(nrow + xB - 4);
            nB1 = *(const float4*)(nrow + xB);
            nB2 = *(const float4*)(nrow + aB2);
        }

        // strided pairs: P[j] = (vA[xA-2+j], vB[xB-2+j]); each value used once
        ull P0 = pk2(cA0.z, cB0.z), P1 = pk2(cA0.w, cB0.w);
        ull P2 = pk2(cA1.x, cB1.x), P3 = pk2(cA1.y, cB1.y);
        ull P4 = pk2(cA1.z, cB1.z), P5 = pk2(cA1.w, cB1.w);
        ull P6 = pk2(cA2.x, cB2.x), P7 = pk2(cA2.y, cB2.y);

        const float* wrow = &wd[(ci * 16 + coo) * 12];
        #pragma unroll
        for (int q = 0; q < 8; ++q) {
            ulonglong2 u01 = *(const ulonglong2*)(wrow + q * 12);
            ulonglong2 u23 = *(const ulonglong2*)(wrow + q * 12 + 4);
            ull W4 = *(const ull*)(wrow + q * 12 + 8);
            ull W0 = u01.x, W1 = u01.y, W2 = u23.x, W3 = u23.y;

            fma2(acc[q][0], P0, W0); fma2(acc[q][0], P1, W1);
            fma2(acc[q][0], P2, W2); fma2(acc[q][0], P3, W3);
            fma2(acc[q][0], P4, W4);
            fma2(acc[q][1], P1, W0); fma2(acc[q][1], P2, W1);
            fma2(acc[q][1], P3, W2); fma2(acc[q][1], P4, W3);
            fma2(acc[q][1], P5, W4);
            fma2(acc[q][2], P2, W0); fma2(acc[q][2], P3, W1);
            fma2(acc[q][2], P4, W2); fma2(acc[q][2], P5, W3);
            fma2(acc[q][2], P6, W4);
            fma2(acc[q][3], P3, W0); fma2(acc[q][3], P4, W1);
            fma2(acc[q][3], P5, W2); fma2(acc[q][3], P6, W3);
            fma2(acc[q][3], P7, W4);
        }
        cA0 = nA0; cA1 = nA1; cA2 = nA2;
        cB0 = nB0; cB1 = nB1; cB2 = nB2;
        rowp = nrow;
    }

    // ---- epilogue ----
    const float ca = (STAGE == 1) ? 1.0f  : (STAGE == 2) ? 0.75f         : (1.0f / 3.0f);
    const float cb = (STAGE == 1) ? 0.0f  : (STAGE == 2) ? 0.25f         : (2.0f / 3.0f);
    const float cc = (STAGE == 1) ? HSTEP : (STAGE == 2) ? 0.25f * HSTEP : (2.0f * HSTEP / 3.0f);

    const float* zb = zin + (size_t)b * CHN * L;
    const float* kb = (STAGE == 1) ? nullptr : kin + (size_t)b * CHN * L;
    float*       ob = out + (size_t)b * CHN * L;

    #pragma unroll
    for (int q = 0; q < 8; ++q) {
        const int co = coo + q;
        const float* zrow = zb + (size_t)co * L;
        float*       orow = ob + (size_t)co * L;

        float cvA[4], cvB[4];
        #pragma unroll
        for (int p = 0; p < 4; ++p) upk2(acc[q][p], cvA[p], cvB[p]);

        #pragma unroll
        for (int s = 0; s < 2; ++s) {
            const int x = (s == 0) ? xA : xB;
            const float* cv = (s == 0) ? cvA : cvB;

            float4 zv = *(const float4*)(zrow + x);
            float r0, r1, r2, r3;
            if (STAGE == 1) {
                r0 = fmaf(cc, cv[0], zv.x); r1 = fmaf(cc, cv[1], zv.y);
                r2 = fmaf(cc, cv[2], zv.z); r3 = fmaf(cc, cv[3], zv.w);
            } else {
                float4 kv = *(const float4*)(kb + (size_t)co * L + x);
                r0 = fmaf(ca, zv.x, fmaf(cb, kv.x, cc * cv[0]));
                r1 = fmaf(ca, zv.y, fmaf(cb, kv.y, cc * cv[1]));
                r2 = fmaf(ca, zv.z, fmaf(cb, kv.z, cc * cv[2]));
                r3 = fmaf(ca, zv.w, fmaf(cb, kv.w, cc * cv[3]));
            }
            store_chunk(orow, x, r0, r1, r2, r3);
        }
    }
}

extern "C" void kernel_launch(void* const* d_in, const int* in_sizes, int n_in,
                              void* d_out, int out_size) {
    const float* z0 = (const float*)d_in[0];
    const float* W  = (const float*)d_in[1];
    float* out = (float*)d_out;

    float *zscr, *k1, *k2;
    cudaGetSymbolAddress((void**)&zscr, g_z);
    cudaGetSymbolAddress((void**)&k1,   g_k1);
    cudaGetSymbolAddress((void**)&k2,   g_k2);

    dim3 grid(L / TILEX, BATCH);   // (16, 32) = 512 CTAs of 128 threads
    for (int s = 0; s < NSTEPS; ++s) {
        const float* src;
        float* dst;
        if (s == 0)      { src = z0;   dst = zscr; }
        else if (s & 1)  { src = zscr; dst = out;  }
        else             { src = out;  dst = zscr; }

        stage_k<1><<<grid, NTHR>>>(src, src, k1, W);
        stage_k<2><<<grid, NTHR>>>(src, k1,  k2, W);
        stage_k<3><<<grid, NTHR>>>(src, k2,  dst, W);
    }
}